// round 9
// baseline (speedup 1.0000x reference)
#include <cuda_runtime.h>

// ---------------- configuration ----------------
#define T        100
#define NTHREADS 256
#define MAXN     2097152

#define S1 112   // y1 / y5 row stride
#define S2 108   // y2 / y3 / y4 row stride

// smem float offsets (all u64-load bases even)
#define OW1   0        // 100   w1T[t*20+co]
#define OB1   100      // 20
#define OW2   120      // 4000  w2T[(ci*5+t)*40+co]
#define OB2   4120     // 40
#define OW3   4160     // 3200  w3T[ci*80+co]
#define OB3   7360     // 80
#define OW4   7440     // 3200  w4T[ci*40+co]
#define OB4   10640    // 40
#define OW5   10680    // 2400  w5T[(ci*3+t)*20+co]
#define OB5   13080    // 20
#define OW6   13100    // 20
#define OB6   13120    // 1
#define ODIF  13122    // 118 floats (110 real, rest zero)
#define OY1   13240    // y1: 20*112 = 2240   (later reused for y5)
#define OY2   15480    // y2: 40*108 = 4320   (later reused for y4)
#define OY3   19800    // y3: 80*108 = 8640
#define SMEM_FLOATS 28440
#define SMEM_BYTES  (SMEM_FLOATS * 4)   // 113760 B -> 2 CTAs/SM (228KB carveout)

__device__ float g_bm[MAXN];

typedef unsigned long long u64;

// ---------------- f32x2 helpers (sm_100+ packed fp32) ----------------
__device__ __forceinline__ u64 splat2(float a) {
    u64 r; asm("mov.b64 %0, {%1, %1};" : "=l"(r) : "f"(a)); return r;
}
__device__ __forceinline__ u64 fma2(u64 a, u64 b, u64 c) {
    u64 d; asm("fma.rn.f32x2 %0, %1, %2, %3;" : "=l"(d) : "l"(a), "l"(b), "l"(c)); return d;
}
__device__ __forceinline__ void unpk(u64 v, float& x, float& y) {
    asm("mov.b64 {%0, %1}, %2;" : "=f"(x), "=f"(y) : "l"(v));
}

__device__ __forceinline__ float elu1(float x) {
    float e = __expf(x) - 1.0f;
    return x > 0.0f ? x : e;
}

__global__ __launch_bounds__(NTHREADS, 2)
void cnn_kernel(const float* __restrict__ uu,
                const float* __restrict__ w1, const float* __restrict__ b1,
                const float* __restrict__ w2, const float* __restrict__ b2,
                const float* __restrict__ w3, const float* __restrict__ b3,
                const float* __restrict__ w4, const float* __restrict__ b4,
                const float* __restrict__ w5, const float* __restrict__ b5,
                const float* __restrict__ w6, const float* __restrict__ b6,
                int N)
{
    extern __shared__ float s[];
    const int tid = threadIdx.x;
    const int g0  = blockIdx.x * T;

    // ---- load + transpose weights ----
    for (int i = tid; i < 100; i += NTHREADS) {           // w1 (20,1,5)
        int co = i / 5, t = i % 5;
        s[OW1 + t * 20 + co] = w1[i];
    }
    for (int i = tid; i < 20; i += NTHREADS)  s[OB1 + i] = b1[i];
    for (int i = tid; i < 4000; i += NTHREADS) {          // w2 (40,20,5)
        int co = i / 100, r = i % 100, ci = r / 5, t = r % 5;
        s[OW2 + (ci * 5 + t) * 40 + co] = w2[i];
    }
    for (int i = tid; i < 40; i += NTHREADS)  s[OB2 + i] = b2[i];
    for (int i = tid; i < 3200; i += NTHREADS) {          // w3 (80,40,1)
        int co = i / 40, ci = i % 40;
        s[OW3 + ci * 80 + co] = w3[i];
    }
    for (int i = tid; i < 80; i += NTHREADS)  s[OB3 + i] = b3[i];
    for (int i = tid; i < 3200; i += NTHREADS) {          // w4 (40,80,1)
        int co = i / 80, ci = i % 80;
        s[OW4 + ci * 40 + co] = w4[i];
    }
    for (int i = tid; i < 40; i += NTHREADS)  s[OB4 + i] = b4[i];
    for (int i = tid; i < 2400; i += NTHREADS) {          // w5 (20,40,3)
        int co = i / 120, r = i % 120, ci = r / 3, t = r % 3;
        s[OW5 + (ci * 3 + t) * 20 + co] = w5[i];
    }
    for (int i = tid; i < 20; i += NTHREADS)  s[OB5 + i] = b5[i];
    for (int i = tid; i < 20; i += NTHREADS)  s[OW6 + i] = w6[i];
    if (tid == 0) s[OB6] = b6[0];

    // ---- dif = avg_diff(uu), window [g0-5, g0+105): 110 real, padded to 118 ----
    for (int ld = tid; ld < 118; ld += NTHREADS) {
        int gd = g0 - 5 + ld;
        float v = 0.0f;
        if (ld < 110 && gd >= 0 && gd < N) {
            if (gd == 0)            v = __ldg(&uu[1]) - __ldg(&uu[0]);
            else if (gd == N - 1)   v = __ldg(&uu[N - 1]) - __ldg(&uu[N - 2]);
            else                    v = 0.5f * (__ldg(&uu[gd + 1]) - __ldg(&uu[gd - 1]));
        }
        s[ODIF + ld] = v;
    }
    __syncthreads();

    // ---- layer 1: 1 -> 20, k=5, pad 2. y1[lp] at gp = g0-3+lp, real lp<106 ----
    // 2240 items fill entire 20x112 region (zeros beyond real range).
    for (int item = tid; item < 20 * 112; item += NTHREADS) {
        int co = item / 112, lp = item % 112;
        float acc = s[OB1 + co];
        #pragma unroll
        for (int t = 0; t < 5; t++)
            acc += s[OW1 + t * 20 + co] * s[ODIF + lp + t];
        int gp = g0 - 3 + lp;
        float v = elu1(acc);
        if (lp >= 106 || gp < 0 || gp >= N) v = 0.0f;
        s[OY1 + co * S1 + lp] = v;
    }
    __syncthreads();

    // ---- layer 2: 20 -> 40, k=5, pad 2. y2[lp] at gp = g0-1+lp, real lp<102 ----
    // 240 items: 20 ch-pairs x 12 posgroups (P_T=9, covers 108)
    if (tid < 240) {
        const int cog = tid / 12, posg = tid % 12;
        const int co0 = cog * 2, lp0 = posg * 9;
        u64 acc[9];
        {
            u64 bp = *reinterpret_cast<const u64*>(&s[OB2 + co0]);
            #pragma unroll
            for (int p = 0; p < 9; p++) acc[p] = bp;
        }
        for (int ci = 0; ci < 20; ci++) {
            const float* yr = &s[OY1 + ci * S1 + lp0];
            const float* wp = &s[OW2 + ci * 5 * 40 + co0];
            u64 as[13];
            #pragma unroll
            for (int j = 0; j < 13; j++) as[j] = splat2(yr[j]);
            #pragma unroll
            for (int t = 0; t < 5; t++) {
                u64 w = *reinterpret_cast<const u64*>(&wp[t * 40]);
                #pragma unroll
                for (int p = 0; p < 9; p++)
                    acc[p] = fma2(w, as[t + p], acc[p]);
            }
        }
        #pragma unroll
        for (int p = 0; p < 9; p++) {
            int lp = lp0 + p, gp = g0 - 1 + lp;
            bool kill = (lp >= 102) | (gp < 0) | (gp >= N);
            float x, y; unpk(acc[p], x, y);
            float v0 = elu1(x), v1 = elu1(y);
            if (kill) { v0 = 0.0f; v1 = 0.0f; }
            s[OY2 + co0 * S2 + lp] = v0;
            s[OY2 + (co0 + 1) * S2 + lp] = v1;
        }
    }
    __syncthreads();

    // ---- layer 3: 40 -> 80, k=1. 255 items: 5 cog (8 ch-pairs) x 51 posg (P_T=2) ----
    if (tid < 255) {
        const int cog = tid / 51, posg = tid % 51;
        const int co0 = cog * 16, lp0 = posg * 2;
        u64 acc[8][2];
        #pragma unroll
        for (int c = 0; c < 8; c++) {
            u64 bp = *reinterpret_cast<const u64*>(&s[OB3 + co0 + 2 * c]);
            acc[c][0] = bp; acc[c][1] = bp;
        }
        for (int ci = 0; ci < 40; ci++) {
            const float* yr = &s[OY2 + ci * S2 + lp0];
            u64 a0 = splat2(yr[0]), a1 = splat2(yr[1]);
            const u64* wp = reinterpret_cast<const u64*>(&s[OW3 + ci * 80 + co0]);
            #pragma unroll
            for (int c = 0; c < 8; c++) {
                u64 w = wp[c];
                acc[c][0] = fma2(w, a0, acc[c][0]);
                acc[c][1] = fma2(w, a1, acc[c][1]);
            }
        }
        #pragma unroll
        for (int c = 0; c < 8; c++)
            #pragma unroll
            for (int p = 0; p < 2; p++) {
                int lp = lp0 + p, gp = g0 - 1 + lp;
                bool kill = (lp >= 102) | (gp < 0) | (gp >= N);
                float x, y; unpk(acc[c][p], x, y);
                float v0 = elu1(x), v1 = elu1(y);
                if (kill) { v0 = 0.0f; v1 = 0.0f; }
                s[OY3 + (co0 + 2 * c) * S2 + lp] = v0;
                s[OY3 + (co0 + 2 * c + 1) * S2 + lp] = v1;
            }
    }
    __syncthreads();

    // ---- layer 4: 80 -> 40, k=1. 255 items: 5 cog (4 ch-pairs) x 51 posg (P_T=2) ----
    // writes y4 into the (dead) y2 region
    if (tid < 255) {
        const int cog = tid / 51, posg = tid % 51;
        const int co0 = cog * 8, lp0 = posg * 2;
        u64 acc[4][2];
        #pragma unroll
        for (int c = 0; c < 4; c++) {
            u64 bp = *reinterpret_cast<const u64*>(&s[OB4 + co0 + 2 * c]);
            acc[c][0] = bp; acc[c][1] = bp;
        }
        for (int ci = 0; ci < 80; ci++) {
            const float* yr = &s[OY3 + ci * S2 + lp0];
            u64 a0 = splat2(yr[0]), a1 = splat2(yr[1]);
            const u64* wp = reinterpret_cast<const u64*>(&s[OW4 + ci * 40 + co0]);
            #pragma unroll
            for (int c = 0; c < 4; c++) {
                u64 w = wp[c];
                acc[c][0] = fma2(w, a0, acc[c][0]);
                acc[c][1] = fma2(w, a1, acc[c][1]);
            }
        }
        #pragma unroll
        for (int c = 0; c < 4; c++)
            #pragma unroll
            for (int p = 0; p < 2; p++) {
                int lp = lp0 + p, gp = g0 - 1 + lp;
                bool kill = (lp >= 102) | (gp < 0) | (gp >= N);
                float x, y; unpk(acc[c][p], x, y);
                float v0 = elu1(x), v1 = elu1(y);
                if (kill) { v0 = 0.0f; v1 = 0.0f; }
                s[OY2 + (co0 + 2 * c) * S2 + lp] = v0;
                s[OY2 + (co0 + 2 * c + 1) * S2 + lp] = v1;
            }
    }
    __syncthreads();

    // ---- layer 5: 40 -> 20, k=3, pad 1. y5[lp] at gp = g0+lp, real lp<100 ----
    // 255 items: 5 cog (2 ch-pairs) x 51 posg (P_T=2). Reads y4 (OY2), writes y5 (OY1).
    if (tid < 255) {
        const int cog = tid / 51, posg = tid % 51;
        const int co0 = cog * 4, lp0 = posg * 2;
        u64 acc[2][2];
        #pragma unroll
        for (int c = 0; c < 2; c++) {
            u64 bp = *reinterpret_cast<const u64*>(&s[OB5 + co0 + 2 * c]);
            acc[c][0] = bp; acc[c][1] = bp;
        }
        for (int ci = 0; ci < 40; ci++) {
            const float* yr = &s[OY2 + ci * S2 + lp0];
            const float* wp = &s[OW5 + ci * 3 * 20 + co0];
            u64 as[4];
            #pragma unroll
            for (int j = 0; j < 4; j++) as[j] = splat2(yr[j]);
            #pragma unroll
            for (int t = 0; t < 3; t++) {
                u64 w0 = *reinterpret_cast<const u64*>(&wp[t * 20]);
                u64 w1 = *reinterpret_cast<const u64*>(&wp[t * 20 + 2]);
                #pragma unroll
                for (int p = 0; p < 2; p++) {
                    acc[0][p] = fma2(w0, as[t + p], acc[0][p]);
                    acc[1][p] = fma2(w1, as[t + p], acc[1][p]);
                }
            }
        }
        #pragma unroll
        for (int c = 0; c < 2; c++)
            #pragma unroll
            for (int p = 0; p < 2; p++) {
                int lp = lp0 + p, gp = g0 + lp;
                bool kill = (lp >= 100) | (gp >= N);
                float x, y; unpk(acc[c][p], x, y);
                float v0 = elu1(x), v1 = elu1(y);
                if (kill) { v0 = 0.0f; v1 = 0.0f; }
                s[OY1 + (co0 + 2 * c) * S1 + lp] = v0;
                s[OY1 + (co0 + 2 * c + 1) * S1 + lp] = v1;
            }
    }
    __syncthreads();

    // ---- layer 6: 20 -> 1, k=1, sigmoid, + 0.1 ----
    for (int lp = tid; lp < T; lp += NTHREADS) {
        int gp = g0 + lp;
        if (gp < N) {
            float acc = s[OB6];
            #pragma unroll
            for (int c = 0; c < 20; c++)
                acc += s[OW6 + c] * s[OY1 + c * S1 + lp];
            float sg = 1.0f / (1.0f + __expf(-acc));
            g_bm[gp] = sg + 0.1f;
        }
    }
}

// ---------------- WENO reconstruction ----------------
__device__ __forceinline__ float weno_flux(float a, float b, float c, float d, float e,
                                           float bm_m1, float bm_0, float bm_p1)
{
    const float C1312 = 13.0f / 12.0f;
    const float E = 1e-13f;
    float f0 = (11.0f * c - 7.0f * d + 2.0f * e) * (1.0f / 6.0f);
    float f1 = (2.0f * b + 5.0f * c - d) * (1.0f / 6.0f);
    float f2 = (-a + 5.0f * b + 2.0f * c) * (1.0f / 6.0f);

    float t0a = c - 2.0f * d + e, t0b = 3.0f * c - 4.0f * d + e;
    float t1a = b - 2.0f * c + d, t1b = b - d;
    float t2a = a - 2.0f * b + c, t2b = a - 4.0f * b + 3.0f * c;
    float b0 = C1312 * t0a * t0a + 0.25f * t0b * t0b;
    float b1 = C1312 * t1a * t1a + 0.25f * t1b * t1b;
    float b2 = C1312 * t2a * t2a + 0.25f * t2b * t2b;

    b0 *= bm_p1;
    b1 *= bm_0;
    b2 *= bm_m1;

    float brs = (b2 - b0) * (b2 - b0);
    float e0 = (E + b0) * (E + b0);
    float e1 = (E + b1) * (E + b1);
    float e2 = (E + b2) * (E + b2);
    float om0 = 0.1f / e0 * (brs + e0);
    float om1 = 0.6f / e1 * (brs + e1);
    float om2 = 0.3f / e2 * (brs + e2);
    return (om0 * f0 + om1 * f1 + om2 * f2) / (om0 + om1 + om2);
}

__global__ void weno_kernel(const float* __restrict__ uu, float* __restrict__ out, int N)
{
    int i = blockIdx.x * blockDim.x + threadIdx.x;
    if (i >= N) return;
    int im2 = i - 2, im1 = i - 1, ip1 = i + 1, ip2 = i + 2, ip3 = i + 3;
    if (im2 < 0) im2 += N;
    if (im1 < 0) im1 += N;
    if (ip1 >= N) ip1 -= N;
    if (ip2 >= N) ip2 -= N;
    if (ip3 >= N) ip3 -= N;

    float umm = __ldg(&uu[im2]), um = __ldg(&uu[im1]), u0 = __ldg(&uu[i]);
    float up  = __ldg(&uu[ip1]), upp = __ldg(&uu[ip2]), uppp = __ldg(&uu[ip3]);
    float bm_m1 = g_bm[im1], bm_0 = g_bm[i], bm_p1 = g_bm[ip1];

    float fluxp = weno_flux(um, u0, up, upp, uppp, bm_m1, bm_0, bm_p1);
    float fluxn = weno_flux(umm, um, u0, up, upp, bm_m1, bm_0, bm_p1);

    out[i] = fluxp - fluxn;
}

extern "C" void kernel_launch(void* const* d_in, const int* in_sizes, int n_in,
                              void* d_out, int out_size)
{
    const float* uu = (const float*)d_in[0];
    const float* w1 = (const float*)d_in[1];
    const float* b1 = (const float*)d_in[2];
    const float* w2 = (const float*)d_in[3];
    const float* b2 = (const float*)d_in[4];
    const float* w3 = (const float*)d_in[5];
    const float* b3 = (const float*)d_in[6];
    const float* w4 = (const float*)d_in[7];
    const float* b4 = (const float*)d_in[8];
    const float* w5 = (const float*)d_in[9];
    const float* b5 = (const float*)d_in[10];
    const float* w6 = (const float*)d_in[11];
    const float* b6 = (const float*)d_in[12];
    float* out = (float*)d_out;
    int N = in_sizes[0];

    cudaFuncSetAttribute(cnn_kernel, cudaFuncAttributeMaxDynamicSharedMemorySize, SMEM_BYTES);

    int nb = (N + T - 1) / T;
    cnn_kernel<<<nb, NTHREADS, SMEM_BYTES>>>(uu, w1, b1, w2, b2, w3, b3, w4, b4,
                                             w5, b5, w6, b6, N);
    weno_kernel<<<(N + 255) / 256, 256>>>(uu, out, N);
}

// round 10
// speedup vs baseline: 1.2582x; 1.2582x over previous
#include <cuda_runtime.h>

// ---------------- configuration ----------------
#define T        100
#define NTHREADS 256
#define MAXN     2097152
#define GRID_P   304     // persistent CTAs: 2 per SM x 152 SMs

#define S1 112   // y1 / y5 row stride
#define S2 108   // y2 / y3 / y4 row stride

// smem float offsets (all u64-load bases even)
#define OW1   0
#define OB1   100
#define OW2   120
#define OB2   4120
#define OW3   4160
#define OB3   7360
#define OW4   7440
#define OB4   10640
#define OW5   10680
#define OB5   13080
#define OW6   13100
#define OB6   13120
#define ODIF  13122
#define OY1   13240
#define OY2   15480
#define OY3   19800
#define SMEM_FLOATS 28440
#define SMEM_BYTES  (SMEM_FLOATS * 4)   // 113760 B -> 2 CTAs/SM

__device__ float g_bm[MAXN];

typedef unsigned long long u64;

__device__ __forceinline__ u64 splat2(float a) {
    u64 r; asm("mov.b64 %0, {%1, %1};" : "=l"(r) : "f"(a)); return r;
}
__device__ __forceinline__ u64 fma2(u64 a, u64 b, u64 c) {
    u64 d; asm("fma.rn.f32x2 %0, %1, %2, %3;" : "=l"(d) : "l"(a), "l"(b), "l"(c)); return d;
}
__device__ __forceinline__ void unpk(u64 v, float& x, float& y) {
    asm("mov.b64 {%0, %1}, %2;" : "=f"(x), "=f"(y) : "l"(v));
}
__device__ __forceinline__ float elu1(float x) {
    float e = __expf(x) - 1.0f;
    return x > 0.0f ? x : e;
}

__global__ __launch_bounds__(NTHREADS, 2)
void cnn_kernel(const float* __restrict__ uu,
                const float* __restrict__ w1, const float* __restrict__ b1,
                const float* __restrict__ w2, const float* __restrict__ b2,
                const float* __restrict__ w3, const float* __restrict__ b3,
                const float* __restrict__ w4, const float* __restrict__ b4,
                const float* __restrict__ w5, const float* __restrict__ b5,
                const float* __restrict__ w6, const float* __restrict__ b6,
                int N, int nTiles)
{
    extern __shared__ float s[];
    const int tid = threadIdx.x;

    // ---- load + transpose weights ONCE per persistent CTA ----
    for (int i = tid; i < 100; i += NTHREADS) {           // w1 (20,1,5)
        int co = i / 5, t = i % 5;
        s[OW1 + t * 20 + co] = w1[i];
    }
    for (int i = tid; i < 20; i += NTHREADS)  s[OB1 + i] = b1[i];
    for (int i = tid; i < 4000; i += NTHREADS) {          // w2 (40,20,5)
        int co = i / 100, r = i % 100, ci = r / 5, t = r % 5;
        s[OW2 + (ci * 5 + t) * 40 + co] = w2[i];
    }
    for (int i = tid; i < 40; i += NTHREADS)  s[OB2 + i] = b2[i];
    for (int i = tid; i < 3200; i += NTHREADS) {          // w3 (80,40,1)
        int co = i / 40, ci = i % 40;
        s[OW3 + ci * 80 + co] = w3[i];
    }
    for (int i = tid; i < 80; i += NTHREADS)  s[OB3 + i] = b3[i];
    for (int i = tid; i < 3200; i += NTHREADS) {          // w4 (40,80,1)
        int co = i / 80, ci = i % 80;
        s[OW4 + ci * 40 + co] = w4[i];
    }
    for (int i = tid; i < 40; i += NTHREADS)  s[OB4 + i] = b4[i];
    for (int i = tid; i < 2400; i += NTHREADS) {          // w5 (20,40,3)
        int co = i / 120, r = i % 120, ci = r / 3, t = r % 3;
        s[OW5 + (ci * 3 + t) * 20 + co] = w5[i];
    }
    for (int i = tid; i < 20; i += NTHREADS)  s[OB5 + i] = b5[i];
    for (int i = tid; i < 20; i += NTHREADS)  s[OW6 + i] = w6[i];
    if (tid == 0) s[OB6] = b6[0];

    for (int tile = blockIdx.x; tile < nTiles; tile += GRID_P) {
        const int g0 = tile * T;

        // ---- dif = avg_diff(uu), window [g0-5, g0+105): 110 real ----
        for (int ld = tid; ld < 118; ld += NTHREADS) {
            int gd = g0 - 5 + ld;
            float v = 0.0f;
            if (ld < 110 && gd >= 0 && gd < N) {
                if (gd == 0)            v = __ldg(&uu[1]) - __ldg(&uu[0]);
                else if (gd == N - 1)   v = __ldg(&uu[N - 1]) - __ldg(&uu[N - 2]);
                else                    v = 0.5f * (__ldg(&uu[gd + 1]) - __ldg(&uu[gd - 1]));
            }
            s[ODIF + ld] = v;
        }
        __syncthreads();   // also orders prev-iter L6 reads of OY1 before new L1 writes

        // ---- layer 1: 1 -> 20, k=5, pad 2. y1[lp] at gp = g0-3+lp, real lp<106 ----
        for (int item = tid; item < 20 * 112; item += NTHREADS) {
            int co = item / 112, lp = item % 112;
            float acc = s[OB1 + co];
            #pragma unroll
            for (int t = 0; t < 5; t++)
                acc += s[OW1 + t * 20 + co] * s[ODIF + lp + t];
            int gp = g0 - 3 + lp;
            float v = elu1(acc);
            if (lp >= 106 || gp < 0 || gp >= N) v = 0.0f;
            s[OY1 + co * S1 + lp] = v;
        }
        __syncthreads();

        // ---- layer 2: 20 -> 40, k=5, pad 2. 240 items: 20 pairs x 12 posg (P_T=9) ----
        if (tid < 240) {
            const int cog = tid / 12, posg = tid % 12;
            const int co0 = cog * 2, lp0 = posg * 9;
            u64 acc[9];
            {
                u64 bp = *reinterpret_cast<const u64*>(&s[OB2 + co0]);
                #pragma unroll
                for (int p = 0; p < 9; p++) acc[p] = bp;
            }
            for (int ci = 0; ci < 20; ci++) {
                const float* yr = &s[OY1 + ci * S1 + lp0];
                const float* wp = &s[OW2 + ci * 5 * 40 + co0];
                u64 as[13];
                #pragma unroll
                for (int j = 0; j < 13; j++) as[j] = splat2(yr[j]);
                #pragma unroll
                for (int t = 0; t < 5; t++) {
                    u64 w = *reinterpret_cast<const u64*>(&wp[t * 40]);
                    #pragma unroll
                    for (int p = 0; p < 9; p++)
                        acc[p] = fma2(w, as[t + p], acc[p]);
                }
            }
            #pragma unroll
            for (int p = 0; p < 9; p++) {
                int lp = lp0 + p, gp = g0 - 1 + lp;
                bool kill = (lp >= 102) | (gp < 0) | (gp >= N);
                float x, y; unpk(acc[p], x, y);
                float v0 = elu1(x), v1 = elu1(y);
                if (kill) { v0 = 0.0f; v1 = 0.0f; }
                s[OY2 + co0 * S2 + lp] = v0;
                s[OY2 + (co0 + 1) * S2 + lp] = v1;
            }
        }
        __syncthreads();

        // ---- layer 3: 40 -> 80, k=1. 255 items: 5 cog (8 pairs) x 51 posg (P_T=2) ----
        if (tid < 255) {
            const int cog = tid / 51, posg = tid % 51;
            const int co0 = cog * 16, lp0 = posg * 2;
            u64 acc[8][2];
            #pragma unroll
            for (int c = 0; c < 8; c++) {
                u64 bp = *reinterpret_cast<const u64*>(&s[OB3 + co0 + 2 * c]);
                acc[c][0] = bp; acc[c][1] = bp;
            }
            for (int ci = 0; ci < 40; ci++) {
                const float* yr = &s[OY2 + ci * S2 + lp0];
                u64 a0 = splat2(yr[0]), a1 = splat2(yr[1]);
                const u64* wp = reinterpret_cast<const u64*>(&s[OW3 + ci * 80 + co0]);
                #pragma unroll
                for (int c = 0; c < 8; c++) {
                    u64 w = wp[c];
                    acc[c][0] = fma2(w, a0, acc[c][0]);
                    acc[c][1] = fma2(w, a1, acc[c][1]);
                }
            }
            #pragma unroll
            for (int c = 0; c < 8; c++)
                #pragma unroll
                for (int p = 0; p < 2; p++) {
                    int lp = lp0 + p, gp = g0 - 1 + lp;
                    bool kill = (lp >= 102) | (gp < 0) | (gp >= N);
                    float x, y; unpk(acc[c][p], x, y);
                    float v0 = elu1(x), v1 = elu1(y);
                    if (kill) { v0 = 0.0f; v1 = 0.0f; }
                    s[OY3 + (co0 + 2 * c) * S2 + lp] = v0;
                    s[OY3 + (co0 + 2 * c + 1) * S2 + lp] = v1;
                }
        }
        __syncthreads();

        // ---- layer 4: 80 -> 40, k=1. 255 items: 5 cog (4 pairs) x 51 posg ----
        if (tid < 255) {
            const int cog = tid / 51, posg = tid % 51;
            const int co0 = cog * 8, lp0 = posg * 2;
            u64 acc[4][2];
            #pragma unroll
            for (int c = 0; c < 4; c++) {
                u64 bp = *reinterpret_cast<const u64*>(&s[OB4 + co0 + 2 * c]);
                acc[c][0] = bp; acc[c][1] = bp;
            }
            for (int ci = 0; ci < 80; ci++) {
                const float* yr = &s[OY3 + ci * S2 + lp0];
                u64 a0 = splat2(yr[0]), a1 = splat2(yr[1]);
                const u64* wp = reinterpret_cast<const u64*>(&s[OW4 + ci * 40 + co0]);
                #pragma unroll
                for (int c = 0; c < 4; c++) {
                    u64 w = wp[c];
                    acc[c][0] = fma2(w, a0, acc[c][0]);
                    acc[c][1] = fma2(w, a1, acc[c][1]);
                }
            }
            #pragma unroll
            for (int c = 0; c < 4; c++)
                #pragma unroll
                for (int p = 0; p < 2; p++) {
                    int lp = lp0 + p, gp = g0 - 1 + lp;
                    bool kill = (lp >= 102) | (gp < 0) | (gp >= N);
                    float x, y; unpk(acc[c][p], x, y);
                    float v0 = elu1(x), v1 = elu1(y);
                    if (kill) { v0 = 0.0f; v1 = 0.0f; }
                    s[OY2 + (co0 + 2 * c) * S2 + lp] = v0;
                    s[OY2 + (co0 + 2 * c + 1) * S2 + lp] = v1;
                }
        }
        __syncthreads();

        // ---- layer 5: 40 -> 20, k=3, pad 1. 255 items: 5 cog (2 pairs) x 51 posg ----
        if (tid < 255) {
            const int cog = tid / 51, posg = tid % 51;
            const int co0 = cog * 4, lp0 = posg * 2;
            u64 acc[2][2];
            #pragma unroll
            for (int c = 0; c < 2; c++) {
                u64 bp = *reinterpret_cast<const u64*>(&s[OB5 + co0 + 2 * c]);
                acc[c][0] = bp; acc[c][1] = bp;
            }
            for (int ci = 0; ci < 40; ci++) {
                const float* yr = &s[OY2 + ci * S2 + lp0];
                const float* wp = &s[OW5 + ci * 3 * 20 + co0];
                u64 as[4];
                #pragma unroll
                for (int j = 0; j < 4; j++) as[j] = splat2(yr[j]);
                #pragma unroll
                for (int t = 0; t < 3; t++) {
                    u64 w0 = *reinterpret_cast<const u64*>(&wp[t * 20]);
                    u64 w1 = *reinterpret_cast<const u64*>(&wp[t * 20 + 2]);
                    #pragma unroll
                    for (int p = 0; p < 2; p++) {
                        acc[0][p] = fma2(w0, as[t + p], acc[0][p]);
                        acc[1][p] = fma2(w1, as[t + p], acc[1][p]);
                    }
                }
            }
            #pragma unroll
            for (int c = 0; c < 2; c++)
                #pragma unroll
                for (int p = 0; p < 2; p++) {
                    int lp = lp0 + p, gp = g0 + lp;
                    bool kill = (lp >= 100) | (gp >= N);
                    float x, y; unpk(acc[c][p], x, y);
                    float v0 = elu1(x), v1 = elu1(y);
                    if (kill) { v0 = 0.0f; v1 = 0.0f; }
                    s[OY1 + (co0 + 2 * c) * S1 + lp] = v0;
                    s[OY1 + (co0 + 2 * c + 1) * S1 + lp] = v1;
                }
        }
        __syncthreads();

        // ---- layer 6: 20 -> 1, k=1, sigmoid, + 0.1 ----
        for (int lp = tid; lp < T; lp += NTHREADS) {
            int gp = g0 + lp;
            if (gp < N) {
                float acc = s[OB6];
                #pragma unroll
                for (int c = 0; c < 20; c++)
                    acc += s[OW6 + c] * s[OY1 + c * S1 + lp];
                float sg = 1.0f / (1.0f + __expf(-acc));
                g_bm[gp] = sg + 0.1f;
            }
        }
        // no barrier here: next iteration's post-dif barrier provides ordering
    }
}

// ---------------- WENO reconstruction ----------------
__device__ __forceinline__ float weno_flux(float a, float b, float c, float d, float e,
                                           float bm_m1, float bm_0, float bm_p1)
{
    const float C1312 = 13.0f / 12.0f;
    const float E = 1e-13f;
    float f0 = (11.0f * c - 7.0f * d + 2.0f * e) * (1.0f / 6.0f);
    float f1 = (2.0f * b + 5.0f * c - d) * (1.0f / 6.0f);
    float f2 = (-a + 5.0f * b + 2.0f * c) * (1.0f / 6.0f);

    float t0a = c - 2.0f * d + e, t0b = 3.0f * c - 4.0f * d + e;
    float t1a = b - 2.0f * c + d, t1b = b - d;
    float t2a = a - 2.0f * b + c, t2b = a - 4.0f * b + 3.0f * c;
    float b0 = C1312 * t0a * t0a + 0.25f * t0b * t0b;
    float b1 = C1312 * t1a * t1a + 0.25f * t1b * t1b;
    float b2 = C1312 * t2a * t2a + 0.25f * t2b * t2b;

    b0 *= bm_p1;
    b1 *= bm_0;
    b2 *= bm_m1;

    float brs = (b2 - b0) * (b2 - b0);
    float e0 = (E + b0) * (E + b0);
    float e1 = (E + b1) * (E + b1);
    float e2 = (E + b2) * (E + b2);
    float om0 = 0.1f / e0 * (brs + e0);
    float om1 = 0.6f / e1 * (brs + e1);
    float om2 = 0.3f / e2 * (brs + e2);
    return (om0 * f0 + om1 * f1 + om2 * f2) / (om0 + om1 + om2);
}

__global__ void weno_kernel(const float* __restrict__ uu, float* __restrict__ out, int N)
{
    int i = blockIdx.x * blockDim.x + threadIdx.x;
    if (i >= N) return;
    int im2 = i - 2, im1 = i - 1, ip1 = i + 1, ip2 = i + 2, ip3 = i + 3;
    if (im2 < 0) im2 += N;
    if (im1 < 0) im1 += N;
    if (ip1 >= N) ip1 -= N;
    if (ip2 >= N) ip2 -= N;
    if (ip3 >= N) ip3 -= N;

    float umm = __ldg(&uu[im2]), um = __ldg(&uu[im1]), u0 = __ldg(&uu[i]);
    float up  = __ldg(&uu[ip1]), upp = __ldg(&uu[ip2]), uppp = __ldg(&uu[ip3]);
    float bm_m1 = g_bm[im1], bm_0 = g_bm[i], bm_p1 = g_bm[ip1];

    float fluxp = weno_flux(um, u0, up, upp, uppp, bm_m1, bm_0, bm_p1);
    float fluxn = weno_flux(umm, um, u0, up, upp, bm_m1, bm_0, bm_p1);

    out[i] = fluxp - fluxn;
}

extern "C" void kernel_launch(void* const* d_in, const int* in_sizes, int n_in,
                              void* d_out, int out_size)
{
    const float* uu = (const float*)d_in[0];
    const float* w1 = (const float*)d_in[1];
    const float* b1 = (const float*)d_in[2];
    const float* w2 = (const float*)d_in[3];
    const float* b2 = (const float*)d_in[4];
    const float* w3 = (const float*)d_in[5];
    const float* b3 = (const float*)d_in[6];
    const float* w4 = (const float*)d_in[7];
    const float* b4 = (const float*)d_in[8];
    const float* w5 = (const float*)d_in[9];
    const float* b5 = (const float*)d_in[10];
    const float* w6 = (const float*)d_in[11];
    const float* b6 = (const float*)d_in[12];
    float* out = (float*)d_out;
    int N = in_sizes[0];

    cudaFuncSetAttribute(cnn_kernel, cudaFuncAttributeMaxDynamicSharedMemorySize, SMEM_BYTES);

    int nTiles = (N + T - 1) / T;
    int grid = nTiles < GRID_P ? nTiles : GRID_P;
    cnn_kernel<<<grid, NTHREADS, SMEM_BYTES>>>(uu, w1, b1, w2, b2, w3, b3, w4, b4,
                                               w5, b5, w6, b6, N, nTiles);
    weno_kernel<<<(N + 255) / 256, 256>>>(uu, out, N);
}

// round 11
// speedup vs baseline: 2.0751x; 1.6493x over previous
#include <cuda_runtime.h>
#include <cuda_bf16.h>
#include <cstdint>

#define NTHREADS 384
#define T        180
#define GRID_P   152
#define MAXN     2097152

typedef unsigned int u32;

// ---- W plane element offsets (bf16 elems) ----
#define PW2 0          // [5][40][40]  = 8000
#define PW3 8000       // [80][56]     = 4480
#define PW4 12480      // [40][84]     = 3360
#define PW5 15840      // [3][24][56]  = 4032
#define PLANE_ELEMS 19872

// ---- smem byte offsets ----
#define OWHI 0
#define OWLO (PLANE_ELEMS*2)            // 39744
#define OSC  (OWLO + PLANE_ELEMS*2)     // 79488 (f32 scalars, 325 floats)
#define SW1 0
#define SB1 100
#define SB2 120
#define SB3 160
#define SB4 240
#define SB5 280      // 24 (20 real + 4 zero)
#define SW6 304
#define SB6 324
#define OBA_HI 81920                    // bufA hi: 192*176 = 33792 B
#define OBA_LO (OBA_HI+33792)           // 115712
#define OBB_HI (OBA_LO+33792)           // 149504 bufB hi: 192*112 = 21504 B
#define OBB_LO (OBB_HI+21504)           // 171008
#define ODIF   (OBB_LO+21504)           // 192512 (196 f32 + guard)
#define SMEM_BYTES (ODIF + 1024)        // 193536

__device__ float g_bm[MAXN];

// ---------------- helpers ----------------
__device__ __forceinline__ u32 sm_u32(const void* p) {
    u32 a;
    asm("{ .reg .u64 t; cvta.to.shared.u64 t, %1; cvt.u32.u64 %0, t; }" : "=r"(a) : "l"(p));
    return a;
}
__device__ __forceinline__ void ldm4(u32 addr, u32& a0, u32& a1, u32& a2, u32& a3) {
    asm volatile("ldmatrix.sync.aligned.m8n8.x4.shared.b16 {%0,%1,%2,%3},[%4];"
                 : "=r"(a0), "=r"(a1), "=r"(a2), "=r"(a3) : "r"(addr));
}
__device__ __forceinline__ u32 lds32(u32 a) {
    u32 v; asm volatile("ld.shared.u32 %0,[%1];" : "=r"(v) : "r"(a)); return v;
}
__device__ __forceinline__ void sts32(u32 a, u32 v) {
    asm volatile("st.shared.u32 [%0],%1;" :: "r"(a), "r"(v));
}
__device__ __forceinline__ void mma16816(float* d, u32 a0, u32 a1, u32 a2, u32 a3, u32 b0, u32 b1) {
    asm volatile("mma.sync.aligned.m16n8k16.row.col.f32.bf16.bf16.f32 "
                 "{%0,%1,%2,%3},{%4,%5,%6,%7},{%8,%9},{%0,%1,%2,%3};"
                 : "+f"(d[0]), "+f"(d[1]), "+f"(d[2]), "+f"(d[3])
                 : "r"(a0), "r"(a1), "r"(a2), "r"(a3), "r"(b0), "r"(b1));
}
__device__ __forceinline__ float elu1(float x) {
    float e = __expf(x) - 1.0f;
    return x > 0.0f ? x : e;
}

// ---------------- MMA conv layer ----------------
// A rows = positions (row index = lp+6), cols = cin (bf16 hi/lo planes).
// W[t][n][KP] bf16, B-frag b0={k=2c,2c+1}@n, b1={k=2c+8,2c+9}@n.
template<int TAPS, int PAD, int KC, int NT, int KP, int NR, int WOFS, int BOFS, int RLO, int RHI>
__device__ __forceinline__ void mma_layer(u32 smb, u32 srcHi, u32 srcLo, int RSsrc,
                                          u32 dstHi, u32 dstLo, int RSdst,
                                          const float* sc, int warp, int lane, int g0, int N)
{
    float acc[NT][4];
    #pragma unroll
    for (int i = 0; i < NT; i++) { acc[i][0] = acc[i][1] = acc[i][2] = acc[i][3] = 0.f; }
    const int m0 = warp * 16;
    const int r = lane & 15, half = lane >> 4;
    const int c = lane & 3, nrow = lane >> 2;
    const u32 wB = smb + OWHI;
    const u32 loDelta = srcLo - srcHi;
    const u32 wPlaneDelta = OWLO - OWHI;

    #pragma unroll
    for (int t = 0; t < TAPS; t++) {
        #pragma unroll
        for (int kc = 0; kc < KC; kc++) {
            u32 aad = srcHi + (u32)((m0 + r + t - PAD) * RSsrc) + kc * 32 + half * 16;
            u32 h0, h1, h2, h3, l0, l1, l2, l3;
            ldm4(aad, h0, h1, h2, h3);
            ldm4(aad + loDelta, l0, l1, l2, l3);
            #pragma unroll
            for (int nt = 0; nt < NT; nt++) {
                int n = nt * 8 + nrow;
                u32 wo = wB + (u32)((WOFS + (t * NR + n) * KP + kc * 16 + 2 * c) * 2);
                u32 bh0 = lds32(wo),              bh1 = lds32(wo + 16);
                u32 bl0 = lds32(wo + wPlaneDelta), bl1 = lds32(wo + wPlaneDelta + 16);
                mma16816(acc[nt], h0, h1, h2, h3, bh0, bh1);
                mma16816(acc[nt], l0, l1, l2, l3, bh0, bh1);
                mma16816(acc[nt], h0, h1, h2, h3, bl0, bl1);
            }
        }
    }
    // epilogue: bias + elu + kill + bf16 split + store
    #pragma unroll
    for (int nt = 0; nt < NT; nt++) {
        int nb = nt * 8 + 2 * c;
        float b0f = sc[BOFS + nb], b1f = sc[BOFS + nb + 1];
        #pragma unroll
        for (int j = 0; j < 2; j++) {
            int row = m0 + nrow + 8 * j;
            int p = g0 + row - 6;
            bool kill = (row < RLO) | (row >= RHI) | (p < 0) | (p >= N);
            float v0 = elu1(acc[nt][2 * j] + b0f);
            float v1 = elu1(acc[nt][2 * j + 1] + b1f);
            if (kill) { v0 = 0.f; v1 = 0.f; }
            __nv_bfloat162 hh = __floats2bfloat162_rn(v0, v1);
            float h0f = __bfloat162float(hh.x), h1f = __bfloat162float(hh.y);
            __nv_bfloat162 ll = __floats2bfloat162_rn(v0 - h0f, v1 - h1f);
            u32 off = (u32)(row * RSdst + nb * 2);
            sts32(dstHi + off, *(u32*)&hh);
            sts32(dstLo + off, *(u32*)&ll);
        }
    }
}

__global__ __launch_bounds__(NTHREADS, 1)
void cnn_kernel(const float* __restrict__ uu,
                const float* __restrict__ w1, const float* __restrict__ b1,
                const float* __restrict__ w2, const float* __restrict__ b2,
                const float* __restrict__ w3, const float* __restrict__ b3,
                const float* __restrict__ w4, const float* __restrict__ b4,
                const float* __restrict__ w5, const float* __restrict__ b5,
                const float* __restrict__ w6, const float* __restrict__ b6,
                int N, int nTiles)
{
    extern __shared__ unsigned char sm[];
    const int tid = threadIdx.x, lane = tid & 31, warp = tid >> 5;
    const u32 smb = sm_u32(sm);
    float* sc = (float*)(sm + OSC);
    __nv_bfloat16* WH = (__nv_bfloat16*)(sm + OWHI);
    __nv_bfloat16* WL = (__nv_bfloat16*)(sm + OWLO);
    float* dif = (float*)(sm + ODIF);
    __nv_bfloat16* bAh = (__nv_bfloat16*)(sm + OBA_HI);
    __nv_bfloat16* bAl = (__nv_bfloat16*)(sm + OBA_LO);

    // ---- scalars ----
    for (int i = tid; i < 100; i += NTHREADS) { int co = i / 5, t = i % 5; sc[SW1 + t * 20 + co] = w1[i]; }
    for (int i = tid; i < 20; i += NTHREADS) sc[SB1 + i] = b1[i];
    for (int i = tid; i < 40; i += NTHREADS) sc[SB2 + i] = b2[i];
    for (int i = tid; i < 80; i += NTHREADS) sc[SB3 + i] = b3[i];
    for (int i = tid; i < 40; i += NTHREADS) sc[SB4 + i] = b4[i];
    for (int i = tid; i < 24; i += NTHREADS) sc[SB5 + i] = (i < 20) ? b5[i] : 0.f;
    for (int i = tid; i < 20; i += NTHREADS) sc[SW6 + i] = w6[i];
    if (tid == 0) sc[SB6] = b6[0];

    // ---- weight planes (bf16 two-term split), zero-padded ----
    #define PUTW(idx, wv) do { float _w = (wv); __nv_bfloat16 _h = __float2bfloat16(_w); \
        WH[idx] = _h; WL[idx] = __float2bfloat16(_w - __bfloat162float(_h)); } while (0)
    for (int i = tid; i < 8000; i += NTHREADS) {         // W2 [5][40][40]
        int t = i / 1600, rr = i % 1600, n = rr / 40, ci = rr % 40;
        PUTW(PW2 + i, ci < 20 ? w2[(n * 20 + ci) * 5 + t] : 0.f);
    }
    for (int i = tid; i < 4480; i += NTHREADS) {         // W3 [80][56]
        int n = i / 56, ci = i % 56;
        PUTW(PW3 + i, ci < 40 ? w3[n * 40 + ci] : 0.f);
    }
    for (int i = tid; i < 3360; i += NTHREADS) {         // W4 [40][84]
        int n = i / 84, ci = i % 84;
        PUTW(PW4 + i, ci < 80 ? w4[n * 80 + ci] : 0.f);
    }
    for (int i = tid; i < 4032; i += NTHREADS) {         // W5 [3][24][56]
        int t = i / 1344, rr = i % 1344, n = rr / 56, ci = rr % 56;
        PUTW(PW5 + i, (n < 20 && ci < 40) ? w5[(n * 40 + ci) * 3 + t] : 0.f);
    }
    // zero activation buffers (once; padded cols stay finite/zero)
    {
        uint4* z = (uint4*)(sm + OBA_HI);
        const int cnt = (33792 * 2 + 21504 * 2) / 16;
        for (int i = tid; i < cnt; i += NTHREADS) z[i] = make_uint4(0, 0, 0, 0);
    }
    __syncthreads();

    const u32 BAH = smb + OBA_HI, BAL = smb + OBA_LO;
    const u32 BBH = smb + OBB_HI, BBL = smb + OBB_LO;

    for (int tile = blockIdx.x; tile < nTiles; tile += GRID_P) {
        const int g0 = tile * T;

        // ---- dif: idx 0..195 <-> lp = idx-8 ----
        for (int ld = tid; ld < 196; ld += NTHREADS) {
            int gd = g0 + ld - 8;
            float v = 0.f;
            if (gd >= 0 && gd < N) {
                if (gd == 0)          v = __ldg(&uu[1]) - __ldg(&uu[0]);
                else if (gd == N - 1) v = __ldg(&uu[N - 1]) - __ldg(&uu[N - 2]);
                else                  v = 0.5f * (__ldg(&uu[gd + 1]) - __ldg(&uu[gd - 1]));
            }
            dif[ld] = v;
        }
        __syncthreads();   // also orders prev-tile L6 reads before L1 writes

        // ---- L1 scalar: 1->20 k5 pad2; row = lp+6, valid rows [2,190) ----
        for (int i = tid; i < 3840; i += NTHREADS) {
            int row = i % 192, co = i / 192;
            float a = sc[SB1 + co];
            #pragma unroll
            for (int t = 0; t < 5; t++) a += sc[SW1 + t * 20 + co] * dif[row + t];
            int p = g0 + row - 6;
            float v = elu1(a);
            if (row < 2 || row >= 190 || p < 0 || p >= N) v = 0.f;
            __nv_bfloat16 h = __float2bfloat16(v);
            bAh[row * 88 + co] = h;
            bAl[row * 88 + co] = __float2bfloat16(v - __bfloat162float(h));
        }
        __syncthreads();

        // L2: 20->40 k5 pad2 | taps5 kc2 NT5 KP40 NR40, rows [4,188)
        mma_layer<5, 2, 2, 5, 40, 40, PW2, SB2, 4, 188>(smb, BAH, BAL, 176, BBH, BBL, 112, sc, warp, lane, g0, N);
        __syncthreads();
        // L3: 40->80 k1 | kc3 NT10 KP56 NR80, rows [4,188)
        mma_layer<1, 0, 3, 10, 56, 80, PW3, SB3, 4, 188>(smb, BBH, BBL, 112, BAH, BAL, 176, sc, warp, lane, g0, N);
        __syncthreads();
        // L4: 80->40 k1 | kc5 NT5 KP84 NR40, rows [4,188)
        mma_layer<1, 0, 5, 5, 84, 40, PW4, SB4, 4, 188>(smb, BAH, BAL, 176, BBH, BBL, 112, sc, warp, lane, g0, N);
        __syncthreads();
        // L5: 40->20 k3 pad1 | taps3 kc3 NT3 KP56 NR24, rows [6,186)
        mma_layer<3, 1, 3, 3, 56, 24, PW5, SB5, 6, 186>(smb, BBH, BBL, 112, BAH, BAL, 176, sc, warp, lane, g0, N);
        __syncthreads();

        // ---- L6: 20->1, sigmoid, +0.1 ----
        for (int i = tid; i < T; i += NTHREADS) {
            int row = i + 6, p = g0 + i;
            if (p < N) {
                float a = sc[SB6];
                #pragma unroll
                for (int cch = 0; cch < 20; cch++)
                    a += sc[SW6 + cch] * (__bfloat162float(bAh[row * 88 + cch]) +
                                          __bfloat162float(bAl[row * 88 + cch]));
                g_bm[p] = 1.f / (1.f + __expf(-a)) + 0.1f;
            }
        }
        // next iteration's post-dif barrier provides ordering
    }
}

// ---------------- WENO reconstruction ----------------
__device__ __forceinline__ float weno_flux(float a, float b, float c, float d, float e,
                                           float bm_m1, float bm_0, float bm_p1)
{
    const float C1312 = 13.0f / 12.0f;
    const float E = 1e-13f;
    float f0 = (11.0f * c - 7.0f * d + 2.0f * e) * (1.0f / 6.0f);
    float f1 = (2.0f * b + 5.0f * c - d) * (1.0f / 6.0f);
    float f2 = (-a + 5.0f * b + 2.0f * c) * (1.0f / 6.0f);

    float t0a = c - 2.0f * d + e, t0b = 3.0f * c - 4.0f * d + e;
    float t1a = b - 2.0f * c + d, t1b = b - d;
    float t2a = a - 2.0f * b + c, t2b = a - 4.0f * b + 3.0f * c;
    float b0 = C1312 * t0a * t0a + 0.25f * t0b * t0b;
    float b1 = C1312 * t1a * t1a + 0.25f * t1b * t1b;
    float b2 = C1312 * t2a * t2a + 0.25f * t2b * t2b;

    b0 *= bm_p1;
    b1 *= bm_0;
    b2 *= bm_m1;

    float brs = (b2 - b0) * (b2 - b0);
    float e0 = (E + b0) * (E + b0);
    float e1 = (E + b1) * (E + b1);
    float e2 = (E + b2) * (E + b2);
    float om0 = 0.1f / e0 * (brs + e0);
    float om1 = 0.6f / e1 * (brs + e1);
    float om2 = 0.3f / e2 * (brs + e2);
    return (om0 * f0 + om1 * f1 + om2 * f2) / (om0 + om1 + om2);
}

__global__ void weno_kernel(const float* __restrict__ uu, float* __restrict__ out, int N)
{
    int i = blockIdx.x * blockDim.x + threadIdx.x;
    if (i >= N) return;
    int im2 = i - 2, im1 = i - 1, ip1 = i + 1, ip2 = i + 2, ip3 = i + 3;
    if (im2 < 0) im2 += N;
    if (im1 < 0) im1 += N;
    if (ip1 >= N) ip1 -= N;
    if (ip2 >= N) ip2 -= N;
    if (ip3 >= N) ip3 -= N;

    float umm = __ldg(&uu[im2]), um = __ldg(&uu[im1]), u0 = __ldg(&uu[i]);
    float up  = __ldg(&uu[ip1]), upp = __ldg(&uu[ip2]), uppp = __ldg(&uu[ip3]);
    float bm_m1 = g_bm[im1], bm_0 = g_bm[i], bm_p1 = g_bm[ip1];

    float fluxp = weno_flux(um, u0, up, upp, uppp, bm_m1, bm_0, bm_p1);
    float fluxn = weno_flux(umm, um, u0, up, upp, bm_m1, bm_0, bm_p1);

    out[i] = fluxp - fluxn;
}

extern "C" void kernel_launch(void* const* d_in, const int* in_sizes, int n_in,
                              void* d_out, int out_size)
{
    const float* uu = (const float*)d_in[0];
    const float* w1 = (const float*)d_in[1];
    const float* b1 = (const float*)d_in[2];
    const float* w2 = (const float*)d_in[3];
    const float* b2 = (const float*)d_in[4];
    const float* w3 = (const float*)d_in[5];
    const float* b3 = (const float*)d_in[6];
    const float* w4 = (const float*)d_in[7];
    const float* b4 = (const float*)d_in[8];
    const float* w5 = (const float*)d_in[9];
    const float* b5 = (const float*)d_in[10];
    const float* w6 = (const float*)d_in[11];
    const float* b6 = (const float*)d_in[12];
    float* out = (float*)d_out;
    int N = in_sizes[0];

    cudaFuncSetAttribute(cnn_kernel, cudaFuncAttributeMaxDynamicSharedMemorySize, SMEM_BYTES);

    int nTiles = (N + T - 1) / T;
    int grid = nTiles < GRID_P ? nTiles : GRID_P;
    cnn_kernel<<<grid, NTHREADS, SMEM_BYTES>>>(uu, w1, b1, w2, b2, w3, b3, w4, b4,
                                               w5, b5, w6, b6, N, nTiles);
    weno_kernel<<<(N + 255) / 256, 256>>>(uu, out, N);
}